// round 17
// baseline (speedup 1.0000x reference)
#include <cuda_runtime.h>
#include <cstdint>

// ---------------------------------------------------------------------------
// P2G quadratic B-spline scatter, 64^3 grid, B<=8 batches.
//
//  - float2 scratch grid (w, w*prob), z-padded rows (68 cells, slot=z+2) so
//    the 3 z-taps always fit two aligned 16B windows -> 18 red.v4 lanes per
//    particle (proven floor; measured ~1.29 cyc/lane, pattern-independent).
//  - no zero kernel: __device__ globals load zeroed; after the divide pass
//    reads the scratch, a trailing cudaMemsetAsync node restores the all-zero
//    invariant (including pad slots). Deterministic: identical ops per call.
// ---------------------------------------------------------------------------

#define GRID_N   64
#define GRID_N3  (GRID_N * GRID_N * GRID_N)
#define B_MAX    8
#define ROWLEN   68                          // 64 + 2 pad each side
#define NROWS    (B_MAX * GRID_N * GRID_N)   // 32768
#define NCELL_SCRATCH (NROWS * ROWLEN)

__device__ float2 g_acc[NCELL_SCRATCH];      // zero-initialized at load

// ---------------------------------------------------------------------------

__device__ __forceinline__ void red_add_v4(float2* addr,
                                           float a, float b, float c, float d) {
    asm volatile("red.global.add.v4.f32 [%0], {%1, %2, %3, %4};"
                 :: "l"(addr), "f"(a), "f"(b), "f"(c), "f"(d)
                 : "memory");
}

__global__ void __launch_bounds__(256)
p2g_scatter_kernel(const float* __restrict__ pos,
                   const float* __restrict__ prob,
                   const int*   __restrict__ bidx,
                   int L) {
    int i = blockIdx.x * blockDim.x + threadIdx.x;
    if (i >= L) return;

    const float EPS_CLIP = 1e-5f;
    const float HI       = 1.0f - 1e-5f;

    float px = fminf(fmaxf(pos[3 * i + 0], EPS_CLIP), HI);
    float py = fminf(fmaxf(pos[3 * i + 1], EPS_CLIP), HI);
    float pz = fminf(fmaxf(pos[3 * i + 2], EPS_CLIP), HI);

    float Xx = px * 64.0f;
    float Xy = py * 64.0f;
    float Xz = pz * 64.0f;

    int bx = (int)Xx;
    int by = (int)Xy;
    int bz = (int)Xz;

    float fx = Xx - (float)bx;
    float fy = Xy - (float)by;
    float fz = Xz - (float)bz;

    float wx[3], wy[3], wz0, wz1, wz2;
    wx[0] = 0.5f * (1.0f - fx) * (1.0f - fx);
    wx[1] = 0.75f - (fx - 0.5f) * (fx - 0.5f);
    wx[2] = 0.5f * fx * fx;
    wy[0] = 0.5f * (1.0f - fy) * (1.0f - fy);
    wy[1] = 0.75f - (fy - 0.5f) * (fy - 0.5f);
    wy[2] = 0.5f * fy * fy;
    wz0 = 0.5f * (1.0f - fz) * (1.0f - fz);
    wz1 = 0.75f - (fz - 0.5f) * (fz - 0.5f);
    wz2 = 0.5f * fz * fz;

    float p_val = prob[i];
    int   brow  = bidx[i] * (GRID_N * GRID_N);

    // shift 3 z-taps (slots bz+1..bz+3) into an aligned 4-cell window
    int zb    = bz + 1;          // in [1, 64]
    int shift = zb & 1;
    int a     = zb - shift;      // even, in [0, 64]; a+3 <= 67

    float z0 = shift ? 0.0f : wz0;
    float z1 = shift ? wz0  : wz1;
    float z2 = shift ? wz1  : wz2;
    float z3 = shift ? wz2  : 0.0f;
    float q0 = z0 * p_val;
    float q1 = z1 * p_val;
    float q2 = z2 * p_val;
    float q3 = z3 * p_val;

    #pragma unroll
    for (int ox = 0; ox < 3; ox++) {
        int tx = bx - 1 + ox;
        if ((unsigned)tx >= (unsigned)GRID_N) continue;
        int xrow = brow + tx * GRID_N;
        #pragma unroll
        for (int oy = 0; oy < 3; oy++) {
            int ty = by - 1 + oy;
            if ((unsigned)ty >= (unsigned)GRID_N) continue;
            float c = wx[ox] * wy[oy];
            float2* base = g_acc + (size_t)(xrow + ty) * ROWLEN + a;
            red_add_v4(base,     c * z0, c * q0, c * z1, c * q1);
            red_add_v4(base + 2, c * z2, c * q2, c * z3, c * q3);
        }
    }
}

// ---------------------------------------------------------------------------
// Divide pass: one thread per 4 output cells (one float4 out store).
// Pure read -> compute -> write; scratch reset is done by the memset node.

__global__ void __launch_bounds__(256)
p2g_finalize_kernel(float* __restrict__ out, int nquads) {
    int t = blockIdx.x * blockDim.x + threadIdx.x;
    if (t >= nquads) return;                 // nquads = B * 4096 * 16

    int row = t >> 4;                        // (b*64 + x)*64 + y
    int zq  = (t & 15) << 2;                 // 0,4,...,60

    const float2* rp = g_acc + (size_t)row * ROWLEN + zq + 2;

    float4 lo = *reinterpret_cast<const float4*>(rp + 0);  // (w0,p0,w1,p1)
    float4 hi = *reinterpret_cast<const float4*>(rp + 2);  // (w2,p2,w3,p3)

    float4 o;
    o.x = lo.y / (lo.x + 1e-7f);
    o.y = lo.w / (lo.z + 1e-7f);
    o.z = hi.y / (hi.x + 1e-7f);
    o.w = hi.w / (hi.z + 1e-7f);
    *reinterpret_cast<float4*>(out + (row << 6) + zq) = o;
}

// ---------------------------------------------------------------------------

extern "C" void kernel_launch(void* const* d_in, const int* in_sizes, int n_in,
                              void* d_out, int out_size) {
    const float* pos  = (const float*)d_in[0];
    const float* prob = (const float*)d_in[1];
    const int*   bidx = (const int*)d_in[2];
    float*       out  = (float*)d_out;

    int L = in_sizes[1];                     // particle count (prob size)
    int B = out_size / GRID_N3;

    p2g_scatter_kernel<<<(L + 255) / 256, 256>>>(pos, prob, bidx, L);

    int nquads = out_size / 4;               // B * 4096 rows * 16 quads
    p2g_finalize_kernel<<<(nquads + 255) / 256, 256>>>(out, nquads);

    // Reset the used scratch region (incl. pad slots) for the next call.
    void* acc_ptr = nullptr;
    cudaGetSymbolAddress(&acc_ptr, g_acc);
    size_t used_bytes = (size_t)B * GRID_N * GRID_N * ROWLEN * sizeof(float2);
    cudaMemsetAsync(acc_ptr, 0, used_bytes, 0);
}